// round 4
// baseline (speedup 1.0000x reference)
#include <cuda_runtime.h>
#include <math.h>

#define NLM 25
#define NPATH 65
#define PENT_STRIDE 256
#define SEG_STRIDE 9
#define PI_F 3.14159265358979323846f
#define CUTOFF_F 5.0f
#define MAXN 10240

// ---------------- scratch (static __device__, no allocations) ----------------
__device__ float  g_y0[MAXN * NLM * 16];           // edge-aggregated features (p=0)
__device__ float  g_y1[MAXN * 2 * NLM * 64];       // TP layer-0 output
__device__ float  g_y2[MAXN * 2 * NLM * 64];       // TP layer-1 output
__device__ double g_Cc[NLM * NLM * NLM];           // complex-basis CG (real valued)
__device__ float  g_CG[NLM * NLM * NLM];           // real-basis CG
__device__ double g_Ure[NLM * NLM];
__device__ double g_Uim[NLM * NLM];
__device__ int2   g_pent[NPATH * PENT_STRIDE];     // entries: (a | b<<5, cg bits)
__device__ int    g_pseg[NPATH * SEG_STRIDE];      // segments: c | cnt<<8
__device__ int    g_psegcnt[NPATH];
__device__ int    g_pathS[NPATH];

__constant__ int c_deg[NLM] = {0,1,1,1,2,2,2,2,2,3,3,3,3,3,3,3,4,4,4,4,4,4,4,4,4};

// ---------------- CG construction (runs every launch; deterministic) ----------------
__device__ __forceinline__ double dfact(int n) {
    const double f[16] = {1.0,1.0,2.0,6.0,24.0,120.0,720.0,5040.0,40320.0,
                          362880.0,3628800.0,39916800.0,479001600.0,
                          6227020800.0,87178291200.0,1307674368000.0};
    return f[n];
}

__device__ double cg_complex(int l1,int m1,int l2,int m2,int l3,int m3) {
    if (m1 + m2 != m3 || l3 < abs(l1 - l2) || l3 > l1 + l2) return 0.0;
    double P = dfact(l1+l2-l3) * dfact(l1-l2+l3) * dfact(-l1+l2+l3) / dfact(l1+l2+l3+1)
             * dfact(l1+m1) * dfact(l1-m1) * dfact(l2+m2) * dfact(l2-m2)
             * dfact(l3+m3) * dfact(l3-m3);
    double sp = sqrt(P);
    int kmin = max(0, max(l2 - l3 - m1, l1 - l3 + m2));
    int kmax = min(l1 + l2 - l3, min(l1 - m1, l2 + m2));
    double s = 0.0;
    for (int k = kmin; k <= kmax; k++) {
        double D = dfact(k) * dfact(l1+l2-l3-k) * dfact(l1-m1-k) * dfact(l2+m2-k)
                 * dfact(l3-l2+m1+k) * dfact(l3-l1-m2+k);
        s += ((k & 1) ? -1.0 : 1.0) * sp / D;
    }
    return sqrt(2.0 * l3 + 1.0) * s;
}

__global__ void k_init_u() {
    int t = threadIdx.x;
    for (int q = t; q < NLM * NLM; q += blockDim.x) { g_Ure[q] = 0.0; g_Uim[q] = 0.0; }
    __syncthreads();
    if (t == 0) {
        const double is2 = 0.7071067811865476;
        for (int l = 0; l <= 4; l++) {
            int off = l * l + l;
            g_Ure[off * NLM + off] = 1.0;
            for (int m = 1; m <= l; m++) {
                double sgn = (m & 1) ? -1.0 : 1.0;
                g_Ure[(off + m) * NLM + (off + m)] = sgn * is2;
                g_Ure[(off + m) * NLM + (off - m)] = is2;
                g_Uim[(off - m) * NLM + (off - m)] = is2;
                g_Uim[(off - m) * NLM + (off + m)] = -sgn * is2;
            }
        }
    }
}

__global__ void k_init_cc() {
    int t = blockIdx.x * blockDim.x + threadIdx.x;
    if (t >= NLM * NLM * NLM) return;
    int a = t / (NLM * NLM), b = (t / NLM) % NLM, c = t % NLM;
    int l1 = c_deg[a], m1 = a - l1 * l1 - l1;
    int l2 = c_deg[b], m2 = b - l2 * l2 - l2;
    int l3 = c_deg[c], m3 = c - l3 * l3 - l3;
    g_Cc[t] = cg_complex(l1, m1, l2, m2, l3, m3);
}

__global__ void k_init_T() {
    int t = blockIdx.x * blockDim.x + threadIdx.x;
    if (t >= NLM * NLM * NLM) return;
    int i = t / (NLM * NLM), j = (t / NLM) % NLM, k = t % NLM;
    int li = c_deg[i], mi = i - li * li - li;
    int lj = c_deg[j], mj = j - lj * lj - lj;
    int lk = c_deg[k], mk = k - lk * lk - lk;
    int acols[2] = {i, li * li + li - mi}; int na = mi ? 2 : 1;
    int bcols[2] = {j, lj * lj + lj - mj}; int nb = mj ? 2 : 1;
    int ccols[2] = {k, lk * lk + lk - mk}; int nc = mk ? 2 : 1;
    double tre = 0.0, tim = 0.0;
    for (int aa = 0; aa < na; aa++) {
        int a = acols[aa];
        double ur1 = g_Ure[i * NLM + a], ui1 = g_Uim[i * NLM + a];
        for (int bb = 0; bb < nb; bb++) {
            int b = bcols[bb];
            double ur2 = g_Ure[j * NLM + b], ui2 = g_Uim[j * NLM + b];
            double wre = ur1 * ur2 - ui1 * ui2;
            double wim = ur1 * ui2 + ui1 * ur2;
            for (int cc = 0; cc < nc; cc++) {
                int c = ccols[cc];
                double cval = g_Cc[(a * NLM + b) * NLM + c];
                if (cval == 0.0) continue;
                double ur3 = g_Ure[k * NLM + c], ui3 = -g_Uim[k * NLM + c]; // conj
                tre += (wre * ur3 - wim * ui3) * cval;
                tim += (wre * ui3 + wim * ur3) * cval;
            }
        }
    }
    double v = tre + tim;
    g_CG[t] = (fabs(v) < 1e-12) ? 0.0f : (float)v;
}

// one thread per path: compact nonzeros into (path, c)-segments
__global__ void k_init_ents() {
    int p = threadIdx.x;
    if (p >= NPATH) return;
    int l1 = 0, l2 = 0, l3 = 0, acc = 0;
    bool found = false;
    for (int a1 = 0; a1 <= 4; a1++)
        for (int a2 = 0; a2 <= 4; a2++) {
            int lo = abs(a1 - a2), hi = min(4, a1 + a2), cnt = hi - lo + 1;
            if (!found) {
                if (p < acc + cnt) { l1 = a1; l2 = a2; l3 = lo + (p - acc); found = true; }
                else acc += cnt;
            }
        }
    g_pathS[p] = (l1 + l2 + l3) & 1;

    int eb = p * PENT_STRIDE;
    int ne = 0, ns = 0;
    for (int c = l3 * l3; c < (l3 + 1) * (l3 + 1); c++) {
        int segstart = ne;
        for (int a = l1 * l1; a < (l1 + 1) * (l1 + 1); a++)
            for (int b = l2 * l2; b < (l2 + 1) * (l2 + 1); b++) {
                float v = g_CG[(a * NLM + b) * NLM + c];
                if (v != 0.0f && ne < PENT_STRIDE) {
                    g_pent[eb + ne] = make_int2(a | (b << 5), __float_as_int(v));
                    ne++;
                }
            }
        int cn = ne - segstart;
        if (cn > 0 && ns < SEG_STRIDE) {
            g_pseg[p * SEG_STRIDE + ns] = c | (cn << 8);
            ns++;
        }
    }
    g_psegcnt[p] = ns;
}

// ---------------- stage kernels ----------------
__global__ void k_zero(int total) {
    int t = blockIdx.x * blockDim.x + threadIdx.x;
    if (t < total) g_y0[t] = 0.0f;
}

// 16 threads per edge (one per radial output channel)
__global__ void k_edge(const int* __restrict__ nbr, const float* __restrict__ disp,
                       const int* __restrict__ Z, const float* __restrict__ Wsp,
                       const float* __restrict__ normp, int E) {
    int t = blockIdx.x * blockDim.x + threadIdx.x;
    int e = t >> 4, rr = t & 15;
    if (e >= E) return;
    int i = nbr[2 * e], j = nbr[2 * e + 1];
    float dx = disp[3 * e], dy = disp[3 * e + 1], dz = disp[3 * e + 2];
    float r = sqrtf(dx * dx + dy * dy + dz * dz + 1e-12f);
    if (r >= CUTOFF_F) return;  // fcut == 0 -> zero contribution
    float inv = 1.0f / r;
    float x = dx * inv, y = dy * inv, z = dz * inv;
    float fcut = 0.5f * (cosf(PI_F * (r * (1.0f / CUTOFF_F))) + 1.0f);

    int Zj = Z[j];
    const float* W = Wsp + Zj * 256 + rr;
    const float gamma = 10.24f;  // (16/5)^2
    float g = 0.0f;
#pragma unroll
    for (int k = 0; k < 16; k++) {
        float d = r - (float)k * (CUTOFF_F / 15.0f);
        float rb = expf(-gamma * d * d);
        g = fmaf(rb, W[k * 16], g);
    }
    g *= fcut / normp[0];

    float x2 = x * x, y2 = y * y, z2 = z * z;
    float Y[NLM];
    Y[0]  = 0.5f * sqrtf(1.0f / PI_F);
    Y[1]  = sqrtf(3.0f / (4.0f * PI_F)) * y;
    Y[2]  = sqrtf(3.0f / (4.0f * PI_F)) * z;
    Y[3]  = sqrtf(3.0f / (4.0f * PI_F)) * x;
    Y[4]  = 0.5f * sqrtf(15.0f / PI_F) * x * y;
    Y[5]  = 0.5f * sqrtf(15.0f / PI_F) * y * z;
    Y[6]  = 0.25f * sqrtf(5.0f / PI_F) * (3.0f * z2 - 1.0f);
    Y[7]  = 0.5f * sqrtf(15.0f / PI_F) * x * z;
    Y[8]  = 0.25f * sqrtf(15.0f / PI_F) * (x2 - y2);
    Y[9]  = 0.25f * sqrtf(35.0f / (2.0f * PI_F)) * y * (3.0f * x2 - y2);
    Y[10] = 0.5f * sqrtf(105.0f / PI_F) * x * y * z;
    Y[11] = 0.25f * sqrtf(21.0f / (2.0f * PI_F)) * y * (5.0f * z2 - 1.0f);
    Y[12] = 0.25f * sqrtf(7.0f / PI_F) * z * (5.0f * z2 - 3.0f);
    Y[13] = 0.25f * sqrtf(21.0f / (2.0f * PI_F)) * x * (5.0f * z2 - 1.0f);
    Y[14] = 0.25f * sqrtf(105.0f / PI_F) * z * (x2 - y2);
    Y[15] = 0.25f * sqrtf(35.0f / (2.0f * PI_F)) * x * (x2 - 3.0f * y2);
    Y[16] = 0.75f * sqrtf(35.0f / PI_F) * x * y * (x2 - y2);
    Y[17] = 0.75f * sqrtf(35.0f / (2.0f * PI_F)) * y * z * (3.0f * x2 - y2);
    Y[18] = 0.75f * sqrtf(5.0f / PI_F) * x * y * (7.0f * z2 - 1.0f);
    Y[19] = 0.75f * sqrtf(5.0f / (2.0f * PI_F)) * y * z * (7.0f * z2 - 3.0f);
    Y[20] = (3.0f / 16.0f) * sqrtf(1.0f / PI_F) * (35.0f * z2 * z2 - 30.0f * z2 + 3.0f);
    Y[21] = 0.75f * sqrtf(5.0f / (2.0f * PI_F)) * x * z * (7.0f * z2 - 3.0f);
    Y[22] = (3.0f / 8.0f) * sqrtf(5.0f / PI_F) * (x2 - y2) * (7.0f * z2 - 1.0f);
    Y[23] = 0.75f * sqrtf(35.0f / (2.0f * PI_F)) * x * z * (x2 - 3.0f * y2);
    Y[24] = (3.0f / 16.0f) * sqrtf(35.0f / PI_F) * (x2 * x2 - 6.0f * x2 * y2 + y2 * y2);

    float* dst = g_y0 + (size_t)i * (NLM * 16) + rr;
#pragma unroll
    for (int lm = 0; lm < NLM; lm++)
        atomicAdd(dst + lm * 16, Y[lm] * g);
}

// ---- TP layer 0: input parity-1 channel is zero -> only w00*a0*b0 survives ----
__global__ void __launch_bounds__(64) k_tp0(const float* __restrict__ W1,
                                            const float* __restrict__ W2,
                                            const float* __restrict__ wp) {
    __shared__ float s_y0[NLM * 16];
    __shared__ float sa[NLM * 64];
    __shared__ float sb[NLM * 64];
    __shared__ float sout[2 * NLM * 64];
    int n = blockIdx.x;
    int g = threadIdx.x;

    const float* yin = g_y0 + (size_t)n * (NLM * 16);
    for (int q = g; q < NLM * 16; q += 64) s_y0[q] = yin[q];
    __syncthreads();

    // dense mixes (p=0 only), W columns in registers
    for (int d = 0; d < 5; d++) {
        float w[16];
        {
            const float* Wb = W1 + (d * 16) * 64 + g;
#pragma unroll
            for (int f = 0; f < 16; f++) w[f] = Wb[f * 64];
            for (int lm = d * d; lm < (d + 1) * (d + 1); lm++) {
                const float4* s4 = (const float4*)&s_y0[lm * 16];
                float acc = 0.0f;
#pragma unroll
                for (int k = 0; k < 4; k++) {
                    float4 v = s4[k];
                    acc = fmaf(v.x, w[4*k+0], acc);
                    acc = fmaf(v.y, w[4*k+1], acc);
                    acc = fmaf(v.z, w[4*k+2], acc);
                    acc = fmaf(v.w, w[4*k+3], acc);
                }
                sa[lm * 64 + g] = acc;
            }
        }
        {
            const float* Wb = W2 + (d * 16) * 64 + g;
#pragma unroll
            for (int f = 0; f < 16; f++) w[f] = Wb[f * 64];
            for (int lm = d * d; lm < (d + 1) * (d + 1); lm++) {
                const float4* s4 = (const float4*)&s_y0[lm * 16];
                float acc = 0.0f;
#pragma unroll
                for (int k = 0; k < 4; k++) {
                    float4 v = s4[k];
                    acc = fmaf(v.x, w[4*k+0], acc);
                    acc = fmaf(v.y, w[4*k+1], acc);
                    acc = fmaf(v.z, w[4*k+2], acc);
                    acc = fmaf(v.w, w[4*k+3], acc);
                }
                sb[lm * 64 + g] = acc;
            }
        }
    }
    __syncthreads();
    for (int q = g; q < 2 * NLM * 64; q += 64) sout[q] = 0.0f;
    __syncthreads();

    for (int p = 0; p < NPATH; p++) {
        float w00 = wp[p * 256 + g];
        int s = g_pathS[p];
        int eb = p * PENT_STRIDE;
        int ns = g_psegcnt[p];
        for (int sg = 0; sg < ns; sg++) {
            int sc = g_pseg[p * SEG_STRIDE + sg];
            int c = sc & 255, cnt = sc >> 8;
            float t00 = 0.0f;
            for (int k = 0; k < cnt; k++) {
                int2 e = g_pent[eb + k];
                int a = e.x & 31, b = (e.x >> 5) & 31;
                float cg = __int_as_float(e.y);
                t00 = fmaf(cg * sa[a * 64 + g], sb[b * 64 + g], t00);
            }
            eb += cnt;
            sout[s * (NLM * 64) + c * 64 + g] += w00 * t00;
        }
    }
    __syncthreads();
    float* yo = g_y1 + (size_t)n * (2 * NLM * 64);
    for (int q = g; q < 2 * NLM * 64; q += 64) yo[q] = sout[q];
}

// ---- TP layer 1: full 2-parity product; sa/sb parity-interleaved ----
__global__ void __launch_bounds__(64) k_tp1(const float* __restrict__ W1,
                                            const float* __restrict__ W2,
                                            const float* __restrict__ wp) {
    __shared__ float ssy[2 * NLM * 64];   // input, reused as output accumulator
    __shared__ float sa[NLM * 128];       // [a][2f+p]
    __shared__ float sb[NLM * 128];
    int n = blockIdx.x;
    int g = threadIdx.x;

    const float* yin = g_y1 + (size_t)n * (2 * NLM * 64);
    for (int q = g; q < 2 * NLM * 64; q += 64) ssy[q] = yin[q];
    __syncthreads();

    for (int p = 0; p < 2; p++) {
        for (int d = 0; d < 5; d++) {
            float w[64];
            {
                const float* Wb = W1 + ((p * 5 + d) * 64) * 64 + g;
#pragma unroll
                for (int f = 0; f < 64; f++) w[f] = Wb[f * 64];
                for (int lm = d * d; lm < (d + 1) * (d + 1); lm++) {
                    const float4* s4 = (const float4*)&ssy[(p * NLM + lm) * 64];
                    float acc = 0.0f;
#pragma unroll
                    for (int k = 0; k < 16; k++) {
                        float4 v = s4[k];
                        acc = fmaf(v.x, w[4*k+0], acc);
                        acc = fmaf(v.y, w[4*k+1], acc);
                        acc = fmaf(v.z, w[4*k+2], acc);
                        acc = fmaf(v.w, w[4*k+3], acc);
                    }
                    sa[lm * 128 + 2 * g + p] = acc;
                }
            }
            {
                const float* Wb = W2 + ((p * 5 + d) * 64) * 64 + g;
#pragma unroll
                for (int f = 0; f < 64; f++) w[f] = Wb[f * 64];
                for (int lm = d * d; lm < (d + 1) * (d + 1); lm++) {
                    const float4* s4 = (const float4*)&ssy[(p * NLM + lm) * 64];
                    float acc = 0.0f;
#pragma unroll
                    for (int k = 0; k < 16; k++) {
                        float4 v = s4[k];
                        acc = fmaf(v.x, w[4*k+0], acc);
                        acc = fmaf(v.y, w[4*k+1], acc);
                        acc = fmaf(v.z, w[4*k+2], acc);
                        acc = fmaf(v.w, w[4*k+3], acc);
                    }
                    sb[lm * 128 + 2 * g + p] = acc;
                }
            }
        }
    }
    __syncthreads();
    for (int q = g; q < 2 * NLM * 64; q += 64) ssy[q] = 0.0f;
    __syncthreads();

    for (int p = 0; p < NPATH; p++) {
        float w00 = wp[p * 256 + g];
        float w01 = wp[p * 256 + 64 + g];
        float w10 = wp[p * 256 + 128 + g];
        float w11 = wp[p * 256 + 192 + g];
        int s = g_pathS[p];
        int eb = p * PENT_STRIDE;
        int ns = g_psegcnt[p];
        for (int sg = 0; sg < ns; sg++) {
            int sc = g_pseg[p * SEG_STRIDE + sg];
            int c = sc & 255, cnt = sc >> 8;
            float t00 = 0.0f, t01 = 0.0f, t10 = 0.0f, t11 = 0.0f;
            for (int k = 0; k < cnt; k++) {
                int2 e = g_pent[eb + k];
                int a = e.x & 31, b = (e.x >> 5) & 31;
                float cg = __int_as_float(e.y);
                float2 av = *(const float2*)&sa[a * 128 + 2 * g];
                float2 bv = *(const float2*)&sb[b * 128 + 2 * g];
                float ca0 = cg * av.x, ca1 = cg * av.y;
                t00 = fmaf(ca0, bv.x, t00);
                t11 = fmaf(ca1, bv.y, t11);
                t01 = fmaf(ca0, bv.y, t01);
                t10 = fmaf(ca1, bv.x, t10);
            }
            eb += cnt;
            ssy[s * (NLM * 64) + c * 64 + g]       += fmaf(w11, t11, w00 * t00);
            ssy[(1 - s) * (NLM * 64) + c * 64 + g] += fmaf(w10, t10, w01 * t01);
        }
    }
    __syncthreads();
    float* yo = g_y2 + (size_t)n * (2 * NLM * 64);
    for (int q = g; q < 2 * NLM * 64; q += 64) yo[q] = ssy[q];
}

// ---- final: te = emb@W_et + b_et; scale, concat, mish ----
__global__ void __launch_bounds__(160) k_final(const int* __restrict__ Z,
                                               const float* __restrict__ emb,
                                               const float* __restrict__ W_et,
                                               const float* __restrict__ b_et,
                                               const float* __restrict__ wf,
                                               float* __restrict__ outp) {
    __shared__ float s_emb[64];
    int n = blockIdx.x;
    int t = threadIdx.x;
    if (t < 64) s_emb[t] = emb[Z[n] * 64 + t];
    __syncthreads();
    if (t >= 144) return;

    float te = b_et[t];
#pragma unroll
    for (int d = 0; d < 64; d++) te = fmaf(s_emb[d], W_et[d * 144 + t], te);

    for (int p = 0; p < 2; p++) {
        for (int lm = 0; lm < NLM; lm++) {
            float yc;
            if (t < 16)
                yc = (p == 0) ? g_y0[(size_t)n * (NLM * 16) + lm * 16 + t] : 0.0f;
            else if (t < 80)
                yc = g_y1[((size_t)n * 2 + p) * (NLM * 64) + lm * 64 + (t - 16)];
            else
                yc = g_y2[((size_t)n * 2 + p) * (NLM * 64) + lm * 64 + (t - 80)];
            float v = te * yc * wf[(p * 5 + c_deg[lm]) * 144 + t];
            if (p == 0 && lm == 0) v += te;
            float sp = log1pf(expf(v));
            float o = v * (1.0f + tanhf(sp));
            outp[(((size_t)n * 2 + p) * NLM + lm) * 144 + t] = o;
        }
    }
}

// ---------------- launch ----------------
extern "C" void kernel_launch(void* const* d_in, const int* in_sizes, int n_in,
                              void* d_out, int out_size) {
    const int*   Z    = (const int*)d_in[0];
    const int*   nbr  = (const int*)d_in[1];
    const float* disp = (const float*)d_in[2];
    const float* Wsp  = (const float*)d_in[3];
    const float* emb  = (const float*)d_in[4];
    const float* W_et = (const float*)d_in[5];
    const float* b_et = (const float*)d_in[6];
    const float* norm = (const float*)d_in[7];
    const float* t0W1 = (const float*)d_in[8];
    const float* t0W2 = (const float*)d_in[9];
    const float* t0wp = (const float*)d_in[10];
    const float* t1W1 = (const float*)d_in[11];
    const float* t1W2 = (const float*)d_in[12];
    const float* t1wp = (const float*)d_in[13];
    const float* wfus = (const float*)d_in[14];
    float* outp = (float*)d_out;

    int N = in_sizes[0];
    int E = in_sizes[1] / 2;

    k_init_u<<<1, 128>>>();
    k_init_cc<<<(NLM*NLM*NLM + 255) / 256, 256>>>();
    k_init_T<<<(NLM*NLM*NLM + 255) / 256, 256>>>();
    k_init_ents<<<1, NPATH>>>();

    int tot0 = N * NLM * 16;
    k_zero<<<(tot0 + 255) / 256, 256>>>(tot0);
    k_edge<<<(E * 16 + 255) / 256, 256>>>(nbr, disp, Z, Wsp, norm, E);
    k_tp0<<<N, 64>>>(t0W1, t0W2, t0wp);
    k_tp1<<<N, 64>>>(t1W1, t1W2, t1wp);
    k_final<<<N, 160>>>(Z, emb, W_et, b_et, wfus, outp);
}